// round 2
// baseline (speedup 1.0000x reference)
#include <cuda_runtime.h>
#include <math.h>

// Problem constants: B=8, H=1024, E=512, V=32000, T=100
#define VOCAB 32000
#define BATCH 8
#define HDIM  1024
#define EDIM  512
#define XV    (HDIM + EDIM)        // 1536
#define XK    (2 * HDIM + EDIM)    // 2560

typedef unsigned long long u64;

// packed f32x2 FMA: d = a*b + c elementwise on (lo,hi) float pairs
__device__ __forceinline__ u64 fma2(u64 a, u64 b, u64 c) {
    u64 d;
    asm("fma.rn.f32x2 %0, %1, %2, %3;" : "=l"(d) : "l"(a), "l"(b), "l"(c));
    return d;
}
__device__ __forceinline__ float f2_lo(u64 a) { return __uint_as_float((unsigned)a); }
__device__ __forceinline__ float f2_hi(u64 a) { return __uint_as_float((unsigned)(a >> 32)); }

#define NTILES (VOCAB / 16)        // 2000 tiles; tile = 4 warps x 4 words
#define GRID_MAIN 592              // 148 SMs x 4 resident CTAs

// ---------------------------------------------------------------------------
// Kernel 1: e_v for ALL words. out[b][w] = exp(tanh(x_v[b].W_V[w] + b_V[w])).
// Persistent-ish: each CTA loads x (48 KB) to smem once, then strides tiles.
// Warp = 4 words; lanes span 128 columns; f32x2 FMAs; W prefetched 1 chunk
// ahead (8 LDG.128 in flight per warp).
// ---------------------------------------------------------------------------
__global__ void __launch_bounds__(128, 4) ev_main_kernel(
    const float* __restrict__ gru,   // [B, H]
    const float* __restrict__ emb,   // [B, E]
    const float* __restrict__ W_V,   // [V, XV]
    const float* __restrict__ b_V,   // [V]
    float* __restrict__ out)         // [B, V]
{
    __shared__ __align__(16) float xs[BATCH][XV];   // 48 KB

    int tid = threadIdx.x;
    // cooperative x_v load: 3072 float4, 24 per thread
    for (int i = tid; i < BATCH * XV / 4; i += 128) {
        int idx = i * 4;
        int b = idx / XV;
        int c = idx - b * XV;
        float4 v;
        if (c < HDIM) v = *(const float4*)&gru[b * HDIM + c];
        else          v = *(const float4*)&emb[b * EDIM + (c - HDIM)];
        *(float4*)&xs[b][c] = v;
    }
    __syncthreads();

    int warp = tid >> 5;
    int lane = tid & 31;
    int lc   = lane * 4;

    for (int tile = blockIdx.x; tile < NTILES; tile += GRID_MAIN) {
        int w0 = tile * 16 + warp * 4;
        const float* Wr = W_V + (size_t)w0 * XV;

        u64 acc[4][8];
#pragma unroll
        for (int wi = 0; wi < 4; wi++)
#pragma unroll
            for (int b = 0; b < 8; b++) acc[wi][b] = 0ull;

        // prefetch chunk 0
        ulonglong2 wv[4];
#pragma unroll
        for (int wi = 0; wi < 4; wi++)
            wv[wi] = *(const ulonglong2*)&Wr[(size_t)wi * XV + lc];

#pragma unroll
        for (int it = 0; it < XV / 128; ++it) {     // 12 chunks of 128 cols
            int cn = (it < 11 ? it + 1 : it) * 128 + lc;  // clamped prefetch (last re-hits L1)
            ulonglong2 wn[4];
#pragma unroll
            for (int wi = 0; wi < 4; wi++)
                wn[wi] = *(const ulonglong2*)&Wr[(size_t)wi * XV + cn];

            int c = it * 128 + lc;
#pragma unroll
            for (int b = 0; b < 8; b++) {
                ulonglong2 xv = *(const ulonglong2*)&xs[b][c];
#pragma unroll
                for (int wi = 0; wi < 4; wi++) {
                    acc[wi][b] = fma2(wv[wi].x, xv.x, acc[wi][b]);
                    acc[wi][b] = fma2(wv[wi].y, xv.y, acc[wi][b]);
                }
            }
#pragma unroll
            for (int wi = 0; wi < 4; wi++) wv[wi] = wn[wi];
        }

        // 32 partial sums per lane -> compacting butterfly (31 shuffles).
        // v[i], i = wi*8 + b. After reduction lane l holds total for index l.
        float v[32];
#pragma unroll
        for (int wi = 0; wi < 4; wi++)
#pragma unroll
            for (int b = 0; b < 8; b++)
                v[wi * 8 + b] = f2_lo(acc[wi][b]) + f2_hi(acc[wi][b]);

#pragma unroll
        for (int d = 16; d > 0; d >>= 1) {
#pragma unroll
            for (int i = 0; i < 32; i++) {
                if (i < d) {
                    float give = (lane & d) ? v[i] : v[i + d];
                    float got  = __shfl_xor_sync(0xffffffffu, give, d);
                    float keep = (lane & d) ? v[i + d] : v[i];
                    v[i] = keep + got;
                }
            }
        }

        int wi = lane >> 3;
        int b  = lane & 7;
        float e = v[0] + b_V[w0 + wi];
        out[(size_t)b * VOCAB + (w0 + wi)] = expf(tanhf(e));
    }
}

// ---------------------------------------------------------------------------
// Kernel 2: fixup for topic words (k>0 => v=0 => energy = tanh(k*e_k)).
// One warp per (b,t); duplicates write identical values (benign race).
// ---------------------------------------------------------------------------
__global__ void __launch_bounds__(256) ek_fixup_kernel(
    const float* __restrict__ gru,
    const float* __restrict__ emb,
    const float* __restrict__ ctx,
    const int*   __restrict__ topic, // [B, T]
    int T,
    const float* __restrict__ W_K,   // [V, XK]
    const float* __restrict__ b_K,   // [V]
    float* __restrict__ out)
{
    int gw   = (int)((blockIdx.x * blockDim.x + threadIdx.x) >> 5);
    int lane = threadIdx.x & 31;
    if (gw >= BATCH * T) return;
    int b = gw / T;
    int t = gw - b * T;

    int w = topic[b * T + t];
    if (w == 0) return;

    int cnt = 0;
    for (int tt = lane; tt < T; tt += 32)
        cnt += (topic[b * T + tt] == w) ? 1 : 0;
#pragma unroll
    for (int o = 16; o > 0; o >>= 1)
        cnt += __shfl_xor_sync(0xffffffffu, cnt, o);

    const float* Wr = W_K + (size_t)w * XK;
    float s = 0.0f;
    for (int c = lane * 4; c < XK; c += 128) {
        float4 wv = *(const float4*)&Wr[c];
        float4 xv;
        if (c < HDIM)      xv = *(const float4*)&gru[b * HDIM + c];
        else if (c < XV)   xv = *(const float4*)&emb[b * EDIM + (c - HDIM)];
        else               xv = *(const float4*)&ctx[b * HDIM + (c - XV)];
        s += wv.x * xv.x + wv.y * xv.y + wv.z * xv.z + wv.w * xv.w;
    }
#pragma unroll
    for (int o = 16; o > 0; o >>= 1)
        s += __shfl_xor_sync(0xffffffffu, s, o);

    if (lane == 0) {
        float e = (float)cnt * (s + b_K[w]);
        out[(size_t)b * VOCAB + w] = expf(tanhf(e));
    }
}

// ---------------------------------------------------------------------------
// Kernel 3: softmax normalize (tanh-bounded => no max pass needed).
// ---------------------------------------------------------------------------
__global__ void __launch_bounds__(1024) softmax_norm_kernel(float* __restrict__ out)
{
    int b = blockIdx.x;
    float* row = out + (size_t)b * VOCAB;

    float s = 0.0f;
    for (int i = threadIdx.x * 4; i < VOCAB; i += 1024 * 4) {
        float4 v = *(const float4*)&row[i];
        s += (v.x + v.y) + (v.z + v.w);
    }

    __shared__ float red[32];
    int lane = threadIdx.x & 31;
    int wid  = threadIdx.x >> 5;
#pragma unroll
    for (int o = 16; o > 0; o >>= 1)
        s += __shfl_xor_sync(0xffffffffu, s, o);
    if (lane == 0) red[wid] = s;
    __syncthreads();
    if (wid == 0) {
        s = red[lane];
#pragma unroll
        for (int o = 16; o > 0; o >>= 1)
            s += __shfl_xor_sync(0xffffffffu, s, o);
        if (lane == 0) red[0] = s;
    }
    __syncthreads();

    float inv = 1.0f / red[0];
    for (int i = threadIdx.x * 4; i < VOCAB; i += 1024 * 4) {
        float4 v = *(const float4*)&row[i];
        v.x *= inv; v.y *= inv; v.z *= inv; v.w *= inv;
        *(float4*)&row[i] = v;
    }
}

// ---------------------------------------------------------------------------
extern "C" void kernel_launch(void* const* d_in, const int* in_sizes, int n_in,
                              void* d_out, int out_size)
{
    const float* gru   = (const float*)d_in[0];
    const float* emb   = (const float*)d_in[1];
    const float* ctx   = (const float*)d_in[2];
    const int*   topic = (const int*)d_in[3];
    int T = in_sizes[3] / BATCH;

    const float* W_V = nullptr; const float* b_V = nullptr;
    const float* W_K = nullptr; const float* b_K = nullptr;
    for (int i = 4; i < n_in; ++i) {
        long sz = (long)in_sizes[i];
        if (sz == (long)VOCAB * XV && i + 1 < n_in) {
            W_V = (const float*)d_in[i];
            b_V = (const float*)d_in[i + 1];
        } else if (sz == (long)VOCAB * XK && i + 1 < n_in) {
            W_K = (const float*)d_in[i];
            b_K = (const float*)d_in[i + 1];
        }
    }

    float* out = (float*)d_out;

    ev_main_kernel<<<GRID_MAIN, 128>>>(gru, emb, W_V, b_V, out);

    int nwarps  = BATCH * T;
    int nblocks = (nwarps * 32 + 255) / 256;
    ek_fixup_kernel<<<nblocks, 256>>>(gru, emb, ctx, topic, T, W_K, b_K, out);

    softmax_norm_kernel<<<BATCH, 1024>>>(out);
}

// round 3
// speedup vs baseline: 4.7151x; 4.7151x over previous
#include <cuda_runtime.h>
#include <math.h>

// Problem constants: B=8, H=1024, E=512, V=32000, T=100
#define VOCAB 32000
#define BATCH 8
#define HDIM  1024
#define EDIM  512
#define XV    (HDIM + EDIM)        // 1536
#define XK    (2 * HDIM + EDIM)    // 2560

#define CHUNK   64                 // columns per chunk (half-warp: 16 lanes x 4)
#define NCHUNK  (XV / CHUNK)       // 24
#define WTILES  (VOCAB / 4)        // 8000 warp-tiles (4 words each)
#define GRID_MAIN 592              // 148 SMs x 4 CTAs
#define NWARPS_TOTAL (GRID_MAIN * 4)

typedef unsigned long long u64;

__device__ __forceinline__ u64 fma2(u64 a, u64 b, u64 c) {
    u64 d;
    asm("fma.rn.f32x2 %0, %1, %2, %3;" : "=l"(d) : "l"(a), "l"(b), "l"(c));
    return d;
}
__device__ __forceinline__ float f2_lo(u64 a) { return __uint_as_float((unsigned)a); }
__device__ __forceinline__ float f2_hi(u64 a) { return __uint_as_float((unsigned)(a >> 32)); }

// self-resetting dynamic work counters (zero-initialized at load; each launch
// leaves them back at 0, so graph replays are deterministic)
__device__ int g_tile = 0;
__device__ int g_done = 0;

// ---------------------------------------------------------------------------
// Kernel 1: e_v for ALL words: out[b][w] = exp(tanh(x_v[b].W_V[w] + b_V[w]))
// Warp = 4 words; lanes 0-15 accumulate words w0,w0+1; lanes 16-31 words
// w0+2,w0+3 (each half covers all columns). f32x2 FMAs, 4-deep W prefetch,
// warp-level dynamic tile scheduling.
// ---------------------------------------------------------------------------
__global__ void __launch_bounds__(128, 4) ev_main_kernel(
    const float* __restrict__ gru,   // [B, H]
    const float* __restrict__ emb,   // [B, E]
    const float* __restrict__ W_V,   // [V, XV]
    const float* __restrict__ b_V,   // [V]
    float* __restrict__ out)         // [B, V]
{
    __shared__ __align__(16) float xs[BATCH][XV];   // exactly 48 KB

    int tid = threadIdx.x;
    for (int i = tid; i < BATCH * XV / 4; i += 128) {
        int idx = i * 4;
        int b = idx / XV;
        int c = idx - b * XV;
        float4 v;
        if (c < HDIM) v = *(const float4*)&gru[b * HDIM + c];
        else          v = *(const float4*)&emb[b * EDIM + (c - HDIM)];
        *(float4*)&xs[b][c] = v;
    }
    __syncthreads();

    int lane = tid & 31;
    int half = lane >> 4;          // 0: words w0,w0+1   1: words w0+2,w0+3
    int l16  = lane & 15;
    int lc   = l16 * 4;            // column offset within chunk

    for (;;) {
        int t = 0;
        if (lane == 0) t = atomicAdd(&g_tile, 1);
        t = __shfl_sync(0xffffffffu, t, 0);
        if (t >= WTILES) break;

        int w0   = t * 4;
        int rowA = w0 + half * 2;
        const float* WA = W_V + (size_t)rowA * XV;
        const float* WB = WA + XV;

        // prefetch chunks 0..3
        ulonglong2 bufA[4], bufB[4];
#pragma unroll
        for (int p = 0; p < 4; p++) {
            bufA[p] = *(const ulonglong2*)&WA[p * CHUNK + lc];
            bufB[p] = *(const ulonglong2*)&WB[p * CHUNK + lc];
        }

        u64 acc[2][8];
#pragma unroll
        for (int b = 0; b < 8; b++) { acc[0][b] = 0ull; acc[1][b] = 0ull; }

#pragma unroll 8
        for (int it = 0; it < NCHUNK; ++it) {
            ulonglong2 wA = bufA[it & 3];
            ulonglong2 wB = bufB[it & 3];
            // issue next prefetch (clamped; tail re-hits L1)
            int nx = it + 4 <= NCHUNK - 1 ? it + 4 : NCHUNK - 1;
            bufA[it & 3] = *(const ulonglong2*)&WA[nx * CHUNK + lc];
            bufB[it & 3] = *(const ulonglong2*)&WB[nx * CHUNK + lc];

            int c = it * CHUNK + lc;
#pragma unroll
            for (int b = 0; b < 8; b++) {
                ulonglong2 x = *(const ulonglong2*)&xs[b][c];
                acc[0][b] = fma2(wA.x, x.x, acc[0][b]);
                acc[0][b] = fma2(wA.y, x.y, acc[0][b]);
                acc[1][b] = fma2(wB.x, x.x, acc[1][b]);
                acc[1][b] = fma2(wB.y, x.y, acc[1][b]);
            }
        }

        // 16 partials per lane; reduce across the 16 lanes of each half-warp
        // with a compacting butterfly (15 shuffles). Index i = wi*8 + b.
        float v[16];
#pragma unroll
        for (int wi = 0; wi < 2; wi++)
#pragma unroll
            for (int b = 0; b < 8; b++)
                v[wi * 8 + b] = f2_lo(acc[wi][b]) + f2_hi(acc[wi][b]);

#pragma unroll
        for (int d = 8; d > 0; d >>= 1) {
#pragma unroll
            for (int i = 0; i < 16; i++) {
                if (i < d) {
                    float give = (l16 & d) ? v[i] : v[i + d];
                    float got  = __shfl_xor_sync(0xffffffffu, give, d);
                    float keep = (l16 & d) ? v[i + d] : v[i];
                    v[i] = keep + got;
                }
            }
        }

        // lane l16 holds index l16 = wi*8 + b
        int wi   = l16 >> 3;
        int b    = l16 & 7;
        int word = w0 + half * 2 + wi;
        float e  = v[0] + b_V[word];
        out[(size_t)b * VOCAB + word] = expf(tanhf(e));
    }

    // last warp to finish resets the counters for the next graph replay
    if (lane == 0) {
        int d = atomicAdd(&g_done, 1);
        if (d == NWARPS_TOTAL - 1) {
            g_tile = 0;
            __threadfence();
            g_done = 0;
        }
    }
}

// ---------------------------------------------------------------------------
// Kernel 2: fixup for topic words (k>0 => v=0 => energy = tanh(k*e_k)).
// One warp per (b,t); duplicates write identical values (benign race).
// ---------------------------------------------------------------------------
__global__ void __launch_bounds__(256) ek_fixup_kernel(
    const float* __restrict__ gru,
    const float* __restrict__ emb,
    const float* __restrict__ ctx,
    const int*   __restrict__ topic, // [B, T]
    int T,
    const float* __restrict__ W_K,   // [V, XK]
    const float* __restrict__ b_K,   // [V]
    float* __restrict__ out)
{
    int gw   = (int)((blockIdx.x * blockDim.x + threadIdx.x) >> 5);
    int lane = threadIdx.x & 31;
    if (gw >= BATCH * T) return;
    int b = gw / T;
    int t = gw - b * T;

    int w = topic[b * T + t];
    if (w == 0) return;

    int cnt = 0;
    for (int tt = lane; tt < T; tt += 32)
        cnt += (topic[b * T + tt] == w) ? 1 : 0;
#pragma unroll
    for (int o = 16; o > 0; o >>= 1)
        cnt += __shfl_xor_sync(0xffffffffu, cnt, o);

    const float* Wr = W_K + (size_t)w * XK;
    float s = 0.0f;
#pragma unroll
    for (int c = lane * 4; c < XK; c += 128) {
        float4 wv = *(const float4*)&Wr[c];
        float4 xv;
        if (c < HDIM)      xv = *(const float4*)&gru[b * HDIM + c];
        else if (c < XV)   xv = *(const float4*)&emb[b * EDIM + (c - HDIM)];
        else               xv = *(const float4*)&ctx[b * HDIM + (c - XV)];
        s += wv.x * xv.x + wv.y * xv.y + wv.z * xv.z + wv.w * xv.w;
    }
#pragma unroll
    for (int o = 16; o > 0; o >>= 1)
        s += __shfl_xor_sync(0xffffffffu, s, o);

    if (lane == 0) {
        float e = (float)cnt * (s + b_K[w]);
        out[(size_t)b * VOCAB + w] = expf(tanhf(e));
    }
}

// ---------------------------------------------------------------------------
// Kernel 3: softmax normalize (tanh-bounded energies => no max pass).
// ---------------------------------------------------------------------------
__global__ void __launch_bounds__(1024) softmax_norm_kernel(float* __restrict__ out)
{
    int b = blockIdx.x;
    float* row = out + (size_t)b * VOCAB;

    float s = 0.0f;
    for (int i = threadIdx.x * 4; i < VOCAB; i += 1024 * 4) {
        float4 v = *(const float4*)&row[i];
        s += (v.x + v.y) + (v.z + v.w);
    }

    __shared__ float red[32];
    int lane = threadIdx.x & 31;
    int wid  = threadIdx.x >> 5;
#pragma unroll
    for (int o = 16; o > 0; o >>= 1)
        s += __shfl_xor_sync(0xffffffffu, s, o);
    if (lane == 0) red[wid] = s;
    __syncthreads();
    if (wid == 0) {
        s = red[lane];
#pragma unroll
        for (int o = 16; o > 0; o >>= 1)
            s += __shfl_xor_sync(0xffffffffu, s, o);
        if (lane == 0) red[0] = s;
    }
    __syncthreads();

    float inv = 1.0f / red[0];
    for (int i = threadIdx.x * 4; i < VOCAB; i += 1024 * 4) {
        float4 v = *(const float4*)&row[i];
        v.x *= inv; v.y *= inv; v.z *= inv; v.w *= inv;
        *(float4*)&row[i] = v;
    }
}

// ---------------------------------------------------------------------------
extern "C" void kernel_launch(void* const* d_in, const int* in_sizes, int n_in,
                              void* d_out, int out_size)
{
    const float* gru   = (const float*)d_in[0];
    const float* emb   = (const float*)d_in[1];
    const float* ctx   = (const float*)d_in[2];
    const int*   topic = (const int*)d_in[3];
    int T = in_sizes[3] / BATCH;

    const float* W_V = nullptr; const float* b_V = nullptr;
    const float* W_K = nullptr; const float* b_K = nullptr;
    for (int i = 4; i < n_in; ++i) {
        long sz = (long)in_sizes[i];
        if (sz == (long)VOCAB * XV && i + 1 < n_in) {
            W_V = (const float*)d_in[i];
            b_V = (const float*)d_in[i + 1];
        } else if (sz == (long)VOCAB * XK && i + 1 < n_in) {
            W_K = (const float*)d_in[i];
            b_K = (const float*)d_in[i + 1];
        }
    }

    float* out = (float*)d_out;

    ev_main_kernel<<<GRID_MAIN, 128>>>(gru, emb, W_V, b_V, out);

    int nwarps  = BATCH * T;
    int nblocks = (nwarps * 32 + 255) / 256;
    ek_fixup_kernel<<<nblocks, 256>>>(gru, emb, ctx, topic, T, W_K, b_K, out);

    softmax_norm_kernel<<<BATCH, 1024>>>(out);
}